// round 5
// baseline (speedup 1.0000x reference)
#include <cuda_runtime.h>
#include <cuda_bf16.h>
#include <cstdint>

#define NUM_ENT 40000
#define ED      256
#define FD      768
#define BATCH   32
#define NE_OUT  (NUM_ENT + 1)
#define ET_LD   40128

// g_Et stores NEGATED values. Column map:
//   col c in [0,40000) : -ent_proj[c] (unity row c+1)
//   col 40000+r        : -other_emb[r] (unity rows 0, 40001..40102)
__device__ float          g_Et[ED * ET_LD];
__device__ __nv_bfloat16  g_Bb[FD * ED];      // proj_W bf16, [n][k] row-major
__device__ float          g_qsum[ED * BATCH];
__device__ int            g_qcol[BATCH * 2];

// ---------------- helpers ----------------
__device__ __forceinline__ unsigned long long addf32x2(unsigned long long a,
                                                       unsigned long long b) {
    unsigned long long r;
    asm("add.rn.f32x2 %0, %1, %2;" : "=l"(r) : "l"(a), "l"(b));
    return r;
}
__device__ __forceinline__ unsigned long long pack2(float x) {
    unsigned long long r;
    asm("mov.b64 %0, {%1,%1};" : "=l"(r) : "f"(x));
    return r;
}
__device__ __forceinline__ void ldsm4(uint32_t r[4], uint32_t addr) {
    asm volatile("ldmatrix.sync.aligned.m8n8.x4.shared.b16 {%0,%1,%2,%3}, [%4];"
                 : "=r"(r[0]), "=r"(r[1]), "=r"(r[2]), "=r"(r[3])
                 : "r"(addr));
}
__device__ __forceinline__ void mma16816(float c[4], const uint32_t a[4],
                                         uint32_t b0, uint32_t b1) {
    asm volatile(
        "mma.sync.aligned.m16n8k16.row.col.f32.bf16.bf16.f32 "
        "{%0,%1,%2,%3}, {%4,%5,%6,%7}, {%8,%9}, {%0,%1,%2,%3};"
        : "+f"(c[0]), "+f"(c[1]), "+f"(c[2]), "+f"(c[3])
        : "r"(a[0]), "r"(a[1]), "r"(a[2]), "r"(a[3]), "r"(b0), "r"(b1));
}
__device__ __forceinline__ uint32_t smaddr(const void* p) {
    return (uint32_t)__cvta_generic_to_shared(p);
}
#define SWZ(off) ((off) ^ (((off) >> 3) & 0x70))

// ---------------- prep: convB + fill edges + decode ids (one kernel) ----------
__global__ void prep_kernel(const float* __restrict__ W,
                            const float* __restrict__ other,
                            const void* __restrict__ ids_raw,
                            const int* __restrict__ mp_ptr) {
    int i = blockIdx.x * 256 + threadIdx.x;
    if (i < FD * ED) g_Bb[i] = __float2bfloat16(W[i]);
    if (i < 103 * ED) {
        int r = i / ED, d = i % ED;
        g_Et[d * ET_LD + NUM_ENT + r] = -other[i];
    }
    if (blockIdx.x == 0 && threadIdx.x < 64) {
        const int t = threadIdx.x;
        const int* p = (const int*)ids_raw;
        // int64 detection: all odd 32-bit words zero across the 32x3 array
        int bad = 0;
#pragma unroll
        for (int k = 0; k < 2; k++) {
            int idx = 1 + 2 * (t + 64 * k);   // odd words, t + {0,64}
            if (idx < BATCH * 3 * 2 - 0 && (t + 64 * k) < 96)
                bad |= (p[idx] != 0);
        }
        unsigned any = __ballot_sync(0xffffffffu, bad);      // lanes 0..31
        unsigned any2 = __ballot_sync(0xffffffffu, bad);     // lanes 32..63 (own warp)
        // combine via shared
        __shared__ int s_is64;
        if (t == 0) s_is64 = 1;
        __syncwarp();
        if ((t < 32 && any) || (t >= 32 && any2)) atomicAnd(&s_is64, 0);
        __syncthreads();
        bool is64 = s_is64 != 0;

        int mp = 2;
        if (mp_ptr) {
            int im = *mp_ptr;
            if (im >= 0 && im < 3) mp = im;
            else {
                float f = __int_as_float(im);
                if (f >= 0.f && f < 3.f) mp = (int)f;
            }
        }
        int b = t >> 1, j = t & 1;
        int col3 = (j < mp) ? j : j + 1;
        int idx  = b * 3 + col3;
        int id   = is64 ? (int)((const long long*)ids_raw)[idx] : p[idx];
        int col  = (id == 0) ? NUM_ENT : (id <= NUM_ENT ? id - 1 : id);
        g_qcol[b * 2 + j] = col;
    }
}

// ---------------- GEMM: Et[n][bm0+m] = -sum_k A[m,k]*W[n,k] ----------------
// BM=128, BN=256(full), BK=64. 512 threads, 16 warps (4m x 4n), warp tile 32x64.
// A: LDG fp32 -> CVT -> STS bf16 (SW128). B: cp.async.cg bf16 (SW128).
#define BM       128
#define BKC      64
#define NCHUNK   (FD / BKC)          // 12
#define SM_A0    0                   // 128*128B = 16 KB
#define SM_A1    16384
#define SM_B0    32768               // 256*128B = 32 KB
#define SM_B1    65536
#define GEMM_SMEM 98304

__global__ void __launch_bounds__(512, 1) gemm_bf16_kernel(const float* __restrict__ A) {
    extern __shared__ char smem[];
    const uint32_t sbase = smaddr(smem);
    const int tid  = threadIdx.x;
    const int lane = tid & 31;
    const int warp = tid >> 5;
    const int wm   = warp >> 2;
    const int wn   = warp & 3;
    const int bm0  = blockIdx.x * BM;

    float acc[2][8][4];
#pragma unroll
    for (int i = 0; i < 2; i++)
#pragma unroll
        for (int j = 0; j < 8; j++)
#pragma unroll
            for (int k = 0; k < 4; k++) acc[i][j][k] = 0.f;

    // A: 128 rows x 16 float4 per chunk; thread -> row tid>>2, float4s (tid&3)*4 +i
    const int arow  = tid >> 2;
    const int af40  = (tid & 3) * 4;
    const bool aok  = (bm0 + arow) < NUM_ENT;
    const float* arow_p = A + (size_t)(aok ? bm0 + arow : 0) * FD;

    float4 ar[4];
    auto loadA = [&](int kc) {
#pragma unroll
        for (int i = 0; i < 4; i++) {
            if (aok) ar[i] = *(const float4*)(arow_p + kc + (af40 + i) * 4);
            else     ar[i] = make_float4(0.f, 0.f, 0.f, 0.f);
        }
    };
    auto stsA = [&](uint32_t abase) {
#pragma unroll
        for (int i = 0; i < 4; i++) {
            __nv_bfloat162 p0 = __floats2bfloat162_rn(ar[i].x, ar[i].y);
            __nv_bfloat162 p1 = __floats2bfloat162_rn(ar[i].z, ar[i].w);
            uint32_t u0 = *(uint32_t*)&p0, u1 = *(uint32_t*)&p1;
            uint32_t off = (uint32_t)(arow * 128 + (af40 + i) * 8);
            asm volatile("st.shared.v2.b32 [%0], {%1,%2};"
                         :: "r"(abase + SWZ(off)), "r"(u0), "r"(u1) : "memory");
        }
    };
    // B: 256 rows x 8 x 16B per chunk = 2048 chunks; 4 per thread
    auto cpB = [&](int kc, uint32_t bbase) {
#pragma unroll
        for (int i = 0; i < 4; i++) {
            int s = i * 512 + tid;
            int r = s >> 3, q = s & 7;
            const __nv_bfloat16* src =
                (const __nv_bfloat16*)g_Bb + r * FD + kc + q * 8;
            uint32_t dst = bbase + SWZ((uint32_t)(r * 128 + q * 16));
            asm volatile("cp.async.cg.shared.global [%0], [%1], 16;"
                         :: "r"(dst), "l"(src) : "memory");
        }
        asm volatile("cp.async.commit_group;" ::: "memory");
    };

    const int quad = lane >> 3, l8 = lane & 7;
    const int arow_l = (quad & 1) * 8 + l8;
    const int acol_q = (quad >> 1) * 8;
    const int brow_l = (quad >> 1) * 8 + l8;
    const int bcol_q = (quad & 1) * 8;

    auto mmaStage = [&](uint32_t abase, uint32_t bbase) {
#pragma unroll
        for (int ks = 0; ks < 4; ks++) {
            const int k0 = ks * 16;
            uint32_t a[2][4], b[4][4];
#pragma unroll
            for (int mf = 0; mf < 2; mf++) {
                uint32_t off = (uint32_t)((wm * 32 + mf * 16 + arow_l) * 128 +
                                          (k0 + acol_q) * 2);
                ldsm4(a[mf], abase + SWZ(off));
            }
#pragma unroll
            for (int nf2 = 0; nf2 < 4; nf2++) {
                uint32_t off = (uint32_t)((wn * 64 + nf2 * 16 + brow_l) * 128 +
                                          (k0 + bcol_q) * 2);
                ldsm4(b[nf2], bbase + SWZ(off));
            }
#pragma unroll
            for (int mf = 0; mf < 2; mf++)
#pragma unroll
                for (int nt = 0; nt < 8; nt++)
                    mma16816(acc[mf][nt], a[mf],
                             b[nt >> 1][(nt & 1) * 2],
                             b[nt >> 1][(nt & 1) * 2 + 1]);
        }
    };

    const uint32_t ab[2] = {sbase + SM_A0, sbase + SM_A1};
    const uint32_t bb[2] = {sbase + SM_B0, sbase + SM_B1};

    // prologue: chunk 0 -> stage 0
    cpB(0, bb[0]);
    loadA(0);
    stsA(ab[0]);

#pragma unroll 1
    for (int c = 0; c < NCHUNK; c++) {
        const int st = c & 1, nst = st ^ 1;
        __syncthreads();                       // stage nst free; STS A(c) visible
        if (c + 1 < NCHUNK) {
            cpB((c + 1) * BKC, bb[nst]);       // DMA next B
            loadA((c + 1) * BKC);              // LDG next A (in-flight)
            asm volatile("cp.async.wait_group 1;" ::: "memory");  // B(c) done
        } else {
            asm volatile("cp.async.wait_group 0;" ::: "memory");
        }
        __syncthreads();                       // all see B(c) complete
        mmaStage(ab[st], bb[st]);
        if (c + 1 < NCHUNK) stsA(ab[nst]);
    }
    __syncthreads();

    // staged, coalesced epilogue: 4 chunks of 64 n-rows, stores NEGATED
    float* s_out = (float*)smem;               // [64][132] = 33.8 KB
    const int g = lane >> 2, tg = lane & 3;
#pragma unroll
    for (int chunk = 0; chunk < 4; chunk++) {
        if (wn == chunk) {
#pragma unroll
            for (int mf = 0; mf < 2; mf++)
#pragma unroll
                for (int nt = 0; nt < 8; nt++) {
                    int srow = nt * 8 + tg * 2;
                    int scol = wm * 32 + mf * 16 + g;
                    s_out[srow * 132 + scol]           = -acc[mf][nt][0];
                    s_out[(srow + 1) * 132 + scol]     = -acc[mf][nt][1];
                    s_out[srow * 132 + scol + 8]       = -acc[mf][nt][2];
                    s_out[(srow + 1) * 132 + scol + 8] = -acc[mf][nt][3];
                }
        }
        __syncthreads();
#pragma unroll
        for (int i = 0; i < 4; i++) {
            int idx = tid + i * 512;
            int n = idx >> 5, m4 = idx & 31;
            if (bm0 + m4 * 4 + 4 <= NUM_ENT) {
                float4 v = *(float4*)&s_out[n * 132 + m4 * 4];
                *(float4*)&g_Et[(size_t)(chunk * 64 + n) * ET_LD + bm0 + m4 * 4] = v;
            }
        }
        __syncthreads();
    }
}

// ---------------- query_sum ----------------
__global__ void __launch_bounds__(256) qsum_kernel() {
    __shared__ float s_red[2][8];
    const int b = blockIdx.x, tid = threadIdx.x;
    const int c0 = g_qcol[b * 2], c1 = g_qcol[b * 2 + 1];

    const int d = tid;
    float v0 = g_Et[d * ET_LD + c0];
    float v1 = g_Et[d * ET_LD + c1];
    float ss0 = v0 * v0, ss1 = v1 * v1;
#pragma unroll
    for (int o = 16; o > 0; o >>= 1) {
        ss0 += __shfl_xor_sync(0xffffffffu, ss0, o);
        ss1 += __shfl_xor_sync(0xffffffffu, ss1, o);
    }
    if ((tid & 31) == 0) { s_red[0][tid >> 5] = ss0; s_red[1][tid >> 5] = ss1; }
    __syncthreads();
    ss0 = 0.f; ss1 = 0.f;
#pragma unroll
    for (int w = 0; w < 8; w++) { ss0 += s_red[0][w]; ss1 += s_red[1][w]; }
    float r0 = -1.0f / fmaxf(sqrtf(ss0), 1e-12f);
    float r1 = -1.0f / fmaxf(sqrtf(ss1), 1e-12f);
    g_qsum[d * BATCH + b] = v0 * r0 + v1 * r1;
}

// ---------------- score ----------------
__global__ void __launch_bounds__(256) score_kernel(float* __restrict__ out) {
    __shared__ unsigned long long sq[ED][4];
    const int tid = threadIdx.x;
    const int by  = blockIdx.y;

    {
        float4* dst = (float4*)&sq[0][0];
#pragma unroll
        for (int i = 0; i < 2; i++) {
            int idx = tid + i * 256;
            int d = idx >> 1, h = idx & 1;
            dst[d * 2 + h] = *(const float4*)(g_qsum + d * BATCH + by * 8 + h * 4);
        }
    }
    __syncthreads();

    int c0 = (blockIdx.x * 256 + tid) * 2;
    const bool active = (c0 <= NUM_ENT);
    const int  cc = active ? c0 : 0;
    const float* ecol = g_Et + cc;

    unsigned long long acc[8];
#pragma unroll
    for (int i = 0; i < 8; i++) acc[i] = 0ULL;

    float2 cur[4], nxt[4];
#pragma unroll
    for (int j = 0; j < 4; j++) cur[j] = *(const float2*)(ecol + j * ET_LD);

    auto body = [&](int d0, const float2 c[4]) {
#pragma unroll
        for (int j = 0; j < 4; j++) {
            unsigned long long e0 = pack2(c[j].x);
            unsigned long long e1 = pack2(c[j].y);
            const unsigned long long* qr = sq[d0 + j];
#pragma unroll
            for (int bp = 0; bp < 4; bp++) {
                unsigned long long q = qr[bp];
                unsigned long long da = addf32x2(q, e0) & 0x7FFFFFFF7FFFFFFFULL;
                unsigned long long db = addf32x2(q, e1) & 0x7FFFFFFF7FFFFFFFULL;
                acc[bp]     = addf32x2(acc[bp], da);
                acc[4 + bp] = addf32x2(acc[4 + bp], db);
            }
        }
    };

    for (int d0 = 0; d0 < ED - 4; d0 += 4) {
#pragma unroll
        for (int j = 0; j < 4; j++)
            nxt[j] = *(const float2*)(ecol + (d0 + 4 + j) * ET_LD);
        body(d0, cur);
#pragma unroll
        for (int j = 0; j < 4; j++) cur[j] = nxt[j];
    }
    body(ED - 4, cur);

    if (active) {
#pragma unroll
        for (int j = 0; j < 2; j++) {
            int c = c0 + j;
            if (c <= NUM_ENT) {
                int e = (c == NUM_ENT) ? 0 : c + 1;
#pragma unroll
                for (int bp = 0; bp < 4; bp++) {
                    unsigned long long a = acc[j * 4 + bp];
                    float lo = __int_as_float((int)(a & 0xffffffffULL));
                    float hi = __int_as_float((int)(a >> 32));
                    int b = 8 * by + 2 * bp;
                    out[(size_t)b * NE_OUT + e]       = -lo;
                    out[(size_t)(b + 1) * NE_OUT + e] = -hi;
                }
            }
        }
    }
}

// ---------------- launcher ----------------
extern "C" void kernel_launch(void* const* d_in, const int* in_sizes, int n_in,
                              void* d_out, int out_size) {
    const float* ent   = (const float*)d_in[0];
    const float* other = (const float*)d_in[1];
    const float* W     = (const float*)d_in[2];
    const void*  ids   = d_in[3];
    const int*   mp    = (n_in > 4) ? (const int*)d_in[4] : nullptr;

    cudaFuncSetAttribute(gemm_bf16_kernel,
                         cudaFuncAttributeMaxDynamicSharedMemorySize, GEMM_SMEM);

    prep_kernel<<<(FD * ED + 255) / 256, 256>>>(W, other, ids, mp);
    gemm_bf16_kernel<<<(NUM_ENT + BM - 1) / BM, 512, GEMM_SMEM>>>(ent);
    qsum_kernel<<<BATCH, 256>>>();
    dim3 sg((NUM_ENT / 2 + 255) / 256 + 1, 4);
    score_kernel<<<sg, 256>>>((float*)d_out);
}